// round 5
// baseline (speedup 1.0000x reference)
#include <cuda_runtime.h>
#include <cuda_bf16.h>
#include <mma.h>

using namespace nvcuda;

// x:(1024,64,256) f32, mask:(64,64,64) f32, w_qkv:(256,768), b_qkv:(768),
// w_proj:(256,256), b_proj:(256) -> out:(1024,64,256) f32

#define NWIN   1024
#define NTOK   64
#define CDIM   256
#define NHEAD  8
#define HD     32
#define MROWS  (NWIN * NTOK)   // 65536

typedef __nv_bfloat16 bf16;

// Static device scratch. NOTE: these symbols are ONLY referenced from device
// code — passing them as kernel arguments from host passes the host shadow
// address (silently readable as zeros on GB300 via ATS). That was the R1-R3 bug.
__device__ __align__(128) float g_Q[NWIN * NHEAD * NTOK * HD];
__device__ __align__(128) float g_K[NWIN * NHEAD * NTOK * HD];
__device__ __align__(128) float g_V[NWIN * NHEAD * NTOK * HD];
__device__ __align__(128) float g_AO[NWIN * NTOK * CDIM];

__device__ __forceinline__ void split_bf16(float x, bf16& hi, bf16& lo) {
    hi = __float2bfloat16_rn(x);
    lo = __float2bfloat16_rn(x - __bfloat162float(hi));
}

// ---------------------------------------------------------------------------
// FP32-emulated GEMM via 3x bf16 wmma (m16n16k16):
//   C(64x64 tile) = A(M x 256) @ B(256 x LDB-slice) + bias
// MODE 0: A from param (x); epilogue scatters g_Q/g_K/g_V (head-major, Q scaled)
// MODE 1: A = g_AO (device symbol, read in device code); plain epilogue to out
// blockDim = 256 (8 warps: 4 along M x 2 along N; warp owns 16 x 32)
// ---------------------------------------------------------------------------
template <int LDB, int MODE>
__global__ __launch_bounds__(256, 2)
void gemm_bf16x3_kernel(const float* __restrict__ A,
                        const float* __restrict__ B,
                        const float* __restrict__ bias,
                        float* __restrict__ out)
{
    __shared__ __align__(32) bf16 Ahi[64][16], Alo[64][16];
    __shared__ __align__(32) bf16 Bhi[16][64], Blo[16][64];
    __shared__ __align__(32) float Cs[64][64];

    const int tid  = threadIdx.x;
    const int warp = tid >> 5;
    const int wm   = warp & 3;   // 0..3: 16 rows each
    const int wn   = warp >> 2;  // 0..1: 32 cols each

    const int bm = blockIdx.y;       // 64-row tile index
    const int bn = blockIdx.x * 64;  // col offset

    const float* Asrc = (MODE == 0) ? A : (const float*)g_AO;

    wmma::fragment<wmma::accumulator, 16, 16, 16, float> acc[2];
    wmma::fill_fragment(acc[0], 0.0f);
    wmma::fill_fragment(acc[1], 0.0f);

    const float* Ap = Asrc + (size_t)(bm * 64) * CDIM;

    for (int k0 = 0; k0 < CDIM; k0 += 16) {
        // Stage A tile: 64 x 16 (one float4 per thread)
        {
            int row = tid >> 2, seg = (tid & 3) * 4;
            float4 v = *(const float4*)(Ap + row * CDIM + k0 + seg);
            split_bf16(v.x, Ahi[row][seg + 0], Alo[row][seg + 0]);
            split_bf16(v.y, Ahi[row][seg + 1], Alo[row][seg + 1]);
            split_bf16(v.z, Ahi[row][seg + 2], Alo[row][seg + 2]);
            split_bf16(v.w, Ahi[row][seg + 3], Alo[row][seg + 3]);
        }
        // Stage B tile: 16 x 64
        {
            int r = tid >> 4, seg = (tid & 15) * 4;
            float4 v = *(const float4*)(B + (size_t)(k0 + r) * LDB + bn + seg);
            split_bf16(v.x, Bhi[r][seg + 0], Blo[r][seg + 0]);
            split_bf16(v.y, Bhi[r][seg + 1], Blo[r][seg + 1]);
            split_bf16(v.z, Bhi[r][seg + 2], Blo[r][seg + 2]);
            split_bf16(v.w, Bhi[r][seg + 3], Blo[r][seg + 3]);
        }
        __syncthreads();

        wmma::fragment<wmma::matrix_a, 16, 16, 16, bf16, wmma::row_major> ah, al;
        wmma::load_matrix_sync(ah, &Ahi[wm * 16][0], 16);
        wmma::load_matrix_sync(al, &Alo[wm * 16][0], 16);
        #pragma unroll
        for (int f = 0; f < 2; f++) {
            wmma::fragment<wmma::matrix_b, 16, 16, 16, bf16, wmma::row_major> bh, bl;
            wmma::load_matrix_sync(bh, &Bhi[0][wn * 32 + f * 16], 64);
            wmma::load_matrix_sync(bl, &Blo[0][wn * 32 + f * 16], 64);
            wmma::mma_sync(acc[f], ah, bh, acc[f]);
            wmma::mma_sync(acc[f], ah, bl, acc[f]);
            wmma::mma_sync(acc[f], al, bh, acc[f]);
        }
        __syncthreads();
    }

    wmma::store_matrix_sync(&Cs[wm * 16][wn * 32],      acc[0], 64, wmma::mem_row_major);
    wmma::store_matrix_sync(&Cs[wm * 16][wn * 32 + 16], acc[1], 64, wmma::mem_row_major);
    __syncthreads();

    if (MODE == 0) {
        // QKV scatter: column j of 768 factors as (m, h, d) = (j/256, (j/32)%8, j%32)
        const float scale = 0.17677669529663687f;  // 1/sqrt(32)
        for (int idx = tid; idx < 4096; idx += 256) {
            int i  = idx >> 6, jj = idx & 63;
            int j  = bn + jj;
            float v = Cs[i][jj] + bias[j];
            int m = j >> 8;
            int h = (j >> 5) & 7;
            int d = j & 31;
            int r = bm * 64 + i;
            int b = r >> 6;
            int n = r & 63;
            int dst = ((b * NHEAD + h) * NTOK + n) * HD + d;
            if (m == 0)      g_Q[dst] = v * scale;
            else if (m == 1) g_K[dst] = v;
            else             g_V[dst] = v;
        }
    } else {
        for (int idx = tid; idx < 4096; idx += 256) {
            int i  = idx >> 6, jj = idx & 63;
            out[(size_t)(bm * 64 + i) * CDIM + bn + jj] = Cs[i][jj] + bias[bn + jj];
        }
    }
}

// ---------------------------------------------------------------------------
// Attention kernel: one CTA per (window b, head h). 128 threads (4 warps).
// S = Q @ K^T (+mask), fp32 softmax, O = P @ V -> g_AO[b, n, h*32+d]
// All matmuls use the 3x bf16 split.
// ---------------------------------------------------------------------------
struct AttnSmem {
    union {
        struct {  // phase 1: Q/K splits for S = Q K^T
            bf16 Qhi[64][32], Qlo[64][32];
            bf16 Khi[64][32], Klo[64][32];
        } qk;
        struct {  // phase 2: P splits for O = P V
            bf16 Phi[64][64];
            bf16 Plo[64][64];
        } p;
    } u;
    bf16  Vhi[64][32], Vlo[64][32];
    float S[64][64];
};

__global__ __launch_bounds__(128, 4)
void attn_kernel(const float* __restrict__ mask)
{
    __shared__ __align__(32) AttnSmem sm;

    const int tid  = threadIdx.x;
    const int warp = tid >> 5;
    const int lane = tid & 31;

    const int bh = blockIdx.x;      // = b*8 + h
    const int b  = bh >> 3;
    const int h  = bh & 7;

    const float* Qg = g_Q + (size_t)bh * NTOK * HD;
    const float* Kg = g_K + (size_t)bh * NTOK * HD;
    const float* Vg = g_V + (size_t)bh * NTOK * HD;

    // Load + split Q, K, V (2048 floats each = 512 float4)
    for (int i = tid; i < 512; i += 128) {
        int r = i >> 3, c = (i & 7) * 4;   // row 0..63, col 0,4,..,28
        float4 q = ((const float4*)Qg)[i];
        float4 k = ((const float4*)Kg)[i];
        float4 v = ((const float4*)Vg)[i];
        split_bf16(q.x, sm.u.qk.Qhi[r][c+0], sm.u.qk.Qlo[r][c+0]);
        split_bf16(q.y, sm.u.qk.Qhi[r][c+1], sm.u.qk.Qlo[r][c+1]);
        split_bf16(q.z, sm.u.qk.Qhi[r][c+2], sm.u.qk.Qlo[r][c+2]);
        split_bf16(q.w, sm.u.qk.Qhi[r][c+3], sm.u.qk.Qlo[r][c+3]);
        split_bf16(k.x, sm.u.qk.Khi[r][c+0], sm.u.qk.Klo[r][c+0]);
        split_bf16(k.y, sm.u.qk.Khi[r][c+1], sm.u.qk.Klo[r][c+1]);
        split_bf16(k.z, sm.u.qk.Khi[r][c+2], sm.u.qk.Klo[r][c+2]);
        split_bf16(k.w, sm.u.qk.Khi[r][c+3], sm.u.qk.Klo[r][c+3]);
        split_bf16(v.x, sm.Vhi[r][c+0], sm.Vlo[r][c+0]);
        split_bf16(v.y, sm.Vhi[r][c+1], sm.Vlo[r][c+1]);
        split_bf16(v.z, sm.Vhi[r][c+2], sm.Vlo[r][c+2]);
        split_bf16(v.w, sm.Vhi[r][c+3], sm.Vlo[r][c+3]);
    }
    __syncthreads();

    // S = Q @ K^T : each warp computes a 16 x 64 strip
    #pragma unroll
    for (int nt = 0; nt < 4; nt++) {
        wmma::fragment<wmma::accumulator, 16, 16, 16, float> acc;
        wmma::fill_fragment(acc, 0.0f);
        #pragma unroll
        for (int k = 0; k < 32; k += 16) {
            wmma::fragment<wmma::matrix_a, 16, 16, 16, bf16, wmma::row_major> ah, al;
            wmma::fragment<wmma::matrix_b, 16, 16, 16, bf16, wmma::col_major> bh, bl;
            wmma::load_matrix_sync(ah, &sm.u.qk.Qhi[warp * 16][k], 32);
            wmma::load_matrix_sync(al, &sm.u.qk.Qlo[warp * 16][k], 32);
            wmma::load_matrix_sync(bh, &sm.u.qk.Khi[nt * 16][k], 32);
            wmma::load_matrix_sync(bl, &sm.u.qk.Klo[nt * 16][k], 32);
            wmma::mma_sync(acc, ah, bh, acc);
            wmma::mma_sync(acc, ah, bl, acc);
            wmma::mma_sync(acc, al, bh, acc);
        }
        wmma::store_matrix_sync(&sm.S[warp * 16][nt * 16], acc, 64, wmma::mem_row_major);
    }
    __syncthreads();

    // Masked fp32 softmax, then split P into bf16 hi/lo (reusing the Q/K region).
    // Each warp: 16 rows; 2 lanes per row, 32 cols each.
    {
        const int row = warp * 16 + (lane >> 1);
        const int c0  = (lane & 1) * 32;
        const int w   = b & 63;   // window index for mask
        const float* mrow = mask + ((size_t)(w * 64 + row)) * 64 + c0;
        float* srow = &sm.S[row][c0];

        float mx = -1e30f;
        #pragma unroll
        for (int c = 0; c < 32; c++) {
            float v = srow[c] + mrow[c];
            srow[c] = v;
            mx = fmaxf(mx, v);
        }
        mx = fmaxf(mx, __shfl_xor_sync(0xffffffffu, mx, 1));

        float sum = 0.0f;
        float e[32];
        #pragma unroll
        for (int c = 0; c < 32; c++) {
            e[c] = __expf(srow[c] - mx);
            sum += e[c];
        }
        sum += __shfl_xor_sync(0xffffffffu, sum, 1);
        float inv = 1.0f / sum;
        __syncthreads();   // all Q/K fragment reads done; safe to overwrite with P
        #pragma unroll
        for (int c = 0; c < 32; c++) {
            float p = e[c] * inv;
            split_bf16(p, sm.u.p.Phi[row][c0 + c], sm.u.p.Plo[row][c0 + c]);
        }
    }
    __syncthreads();

    // O = P @ V : each warp 16 x 32, store directly to g_AO (b, n, h*32+d)
    float* Og = g_AO + (size_t)(b * NTOK) * CDIM + h * HD;
    #pragma unroll
    for (int nt = 0; nt < 2; nt++) {
        wmma::fragment<wmma::accumulator, 16, 16, 16, float> acc;
        wmma::fill_fragment(acc, 0.0f);
        #pragma unroll
        for (int k = 0; k < 64; k += 16) {
            wmma::fragment<wmma::matrix_a, 16, 16, 16, bf16, wmma::row_major> ph, pl;
            wmma::fragment<wmma::matrix_b, 16, 16, 16, bf16, wmma::row_major> vh, vl;
            wmma::load_matrix_sync(ph, &sm.u.p.Phi[warp * 16][k], 64);
            wmma::load_matrix_sync(pl, &sm.u.p.Plo[warp * 16][k], 64);
            wmma::load_matrix_sync(vh, &sm.Vhi[k][nt * 16], 32);
            wmma::load_matrix_sync(vl, &sm.Vlo[k][nt * 16], 32);
            wmma::mma_sync(acc, ph, vh, acc);
            wmma::mma_sync(acc, ph, vl, acc);
            wmma::mma_sync(acc, pl, vh, acc);
        }
        wmma::store_matrix_sync(Og + (size_t)(warp * 16) * CDIM + nt * 16, acc, CDIM,
                                wmma::mem_row_major);
    }
}

extern "C" void kernel_launch(void* const* d_in, const int* in_sizes, int n_in,
                              void* d_out, int out_size)
{
    // Input identification by element count (confirmed matching in R3/R4),
    // with byte-count then positional fallback.
    const int elems[6] = {16777216, 262144, 196608, 768, 65536, 256};
    const float* p[6] = {nullptr, nullptr, nullptr, nullptr, nullptr, nullptr};
    bool done = false;
    for (int pass = 0; pass < 2 && !done; pass++) {
        long long mult = (pass == 0) ? 1 : 4;
        const float* q[6] = {nullptr, nullptr, nullptr, nullptr, nullptr, nullptr};
        for (int i = 0; i < n_in; i++)
            for (int j = 0; j < 6; j++)
                if ((long long)in_sizes[i] == (long long)elems[j] * mult && q[j] == nullptr)
                    q[j] = (const float*)d_in[i];
        bool all = true;
        for (int j = 0; j < 6; j++) if (q[j] == nullptr) all = false;
        if (all) { for (int j = 0; j < 6; j++) p[j] = q[j]; done = true; }
    }
    if (!done)
        for (int j = 0; j < 6 && j < n_in; j++) p[j] = (const float*)d_in[j];

    const float* x      = p[0];
    const float* mask   = p[1];
    const float* w_qkv  = p[2];
    const float* b_qkv  = p[3];
    const float* w_proj = p[4];
    const float* b_proj = p[5];
    float* out = (float*)d_out;

    // 1) QKV projection: (65536 x 256) @ (256 x 768) -> g_Q/g_K/g_V
    {
        dim3 grid(768 / 64, MROWS / 64);
        gemm_bf16x3_kernel<768, 0><<<grid, 256>>>(x, w_qkv, b_qkv, nullptr);
    }
    // 2) Windowed attention per (window, head)
    attn_kernel<<<NWIN * NHEAD, 128>>>(mask);
    // 3) Output projection: (65536 x 256) @ g_AO read in-kernel -> out
    {
        dim3 grid(CDIM / 64, MROWS / 64);
        gemm_bf16x3_kernel<CDIM, 1><<<grid, 256>>>(nullptr, w_proj, b_proj, out);
    }
}

// round 7
// speedup vs baseline: 2.1484x; 2.1484x over previous
#include <cuda_runtime.h>
#include <cuda_bf16.h>
#include <mma.h>

using namespace nvcuda;

// x:(1024,64,256) f32, mask:(64,64,64) f32, w_qkv:(256,768), b_qkv:(768),
// w_proj:(256,256), b_proj:(256) -> out:(1024,64,256) f32

#define NWIN   1024
#define NTOK   64
#define CDIM   256
#define NHEAD  8
#define HD     32
#define MROWS  (NWIN * NTOK)   // 65536

typedef __nv_bfloat16 bf16;

// Static device scratch. Only referenced from device code (host-side use of a
// __device__ symbol as a kernel arg passes the host shadow — the R1-R3 bug).
__device__ __align__(128) float g_Q[NWIN * NHEAD * NTOK * HD];
__device__ __align__(128) float g_K[NWIN * NHEAD * NTOK * HD];
__device__ __align__(128) float g_V[NWIN * NHEAD * NTOK * HD];
__device__ __align__(128) float g_AO[NWIN * NTOK * CDIM];

__device__ __forceinline__ void split_bf16(float x, bf16& hi, bf16& lo) {
    hi = __float2bfloat16_rn(x);
    lo = __float2bfloat16_rn(x - __bfloat162float(hi));
}

// ---------------------------------------------------------------------------
// FP32-emulated GEMM via 3x bf16 wmma, 128x128 CTA tile, K-chunk 32,
// double-buffered smem, 512 threads (16 warps in 4x4; warp tile 32x32).
// smem plane layout (slot = plane index): hi planes at slots {0,1} = buf,
// lo planes at slots {2,3} = buf + 2.  (R6 bug: mixed conventions -> OOB.)
// MODE 0: A = x param; epilogue scatters g_Q/g_K/g_V (head-major, Q scaled)
// MODE 1: A = g_AO (device symbol); plain epilogue to out
// ---------------------------------------------------------------------------
#define SA_STRIDE 40    // 32 + 8 pad (bf16 elems); row = 80B, 16B-aligned
#define SB_STRIDE 136   // 128 + 8 pad; row = 272B, 16B-aligned
#define SA_PLANE  (128 * SA_STRIDE)          // bf16 elems per A plane
#define SB_PLANE  (32 * SB_STRIDE)           // bf16 elems per B plane
#define SA_BYTES  (4 * SA_PLANE * 2)         // 4 planes = 40960 B
#define SB_BYTES  (4 * SB_PLANE * 2)         // 4 planes = 34816 B
#define GEMM_SMEM (SA_BYTES + SB_BYTES)      // 75776 (Cs 64KB unions at offset 0)

template <int LDB, int MODE>
__global__ __launch_bounds__(512, 2)
void gemm_bf16x3_kernel(const float* __restrict__ A,
                        const float* __restrict__ B,
                        const float* __restrict__ bias,
                        float* __restrict__ out)
{
    extern __shared__ __align__(128) char smem_raw[];
    bf16*  sA = (bf16*)smem_raw;
    bf16*  sB = (bf16*)(smem_raw + SA_BYTES);
    float* Cs = (float*)smem_raw;                   // epilogue union, 128x128

    const int tid  = threadIdx.x;
    const int warp = tid >> 5;
    const int wm   = warp & 3;    // 0..3 -> rows wm*32
    const int wn   = warp >> 2;   // 0..3 -> cols wn*32

    const int bm = blockIdx.y;        // 128-row tile
    const int bn = blockIdx.x * 128;  // col offset

    const float* Asrc = (MODE == 0) ? A : (const float*)g_AO;
    const float* Ap   = Asrc + (size_t)bm * 128 * CDIM;

    const int a_row0 = tid >> 3,  a_ks = (tid & 7) * 4;
    const int b_k0   = tid >> 5,  b_cs = (tid & 31) * 4;

    wmma::fragment<wmma::accumulator, 16, 16, 16, float> acc[2][2];
    #pragma unroll
    for (int i = 0; i < 2; i++)
        #pragma unroll
        for (int j = 0; j < 2; j++) wmma::fill_fragment(acc[i][j], 0.0f);

    float4 ra[2], rb[2];

    // ---- preload chunk 0 into buf 0 ----
    #pragma unroll
    for (int it = 0; it < 2; it++) {
        ra[it] = *(const float4*)(Ap + (size_t)(a_row0 + it * 64) * CDIM + a_ks);
        rb[it] = *(const float4*)(B + (size_t)(b_k0 + it * 16) * LDB + bn + b_cs);
    }
    #pragma unroll
    for (int it = 0; it < 2; it++) {
        int row = a_row0 + it * 64;
        bf16* ah = sA + (size_t)row * SA_STRIDE + a_ks;   // buf0 hi (slot 0)
        bf16* al = ah + 2 * SA_PLANE;                     // buf0 lo (slot 2)
        split_bf16(ra[it].x, ah[0], al[0]);
        split_bf16(ra[it].y, ah[1], al[1]);
        split_bf16(ra[it].z, ah[2], al[2]);
        split_bf16(ra[it].w, ah[3], al[3]);
        int k = b_k0 + it * 16;
        bf16* bh = sB + (size_t)k * SB_STRIDE + b_cs;     // buf0 hi (slot 0)
        bf16* bl = bh + 2 * SB_PLANE;                     // buf0 lo (slot 2)
        split_bf16(rb[it].x, bh[0], bl[0]);
        split_bf16(rb[it].y, bh[1], bl[1]);
        split_bf16(rb[it].z, bh[2], bl[2]);
        split_bf16(rb[it].w, bh[3], bl[3]);
    }
    __syncthreads();

    #pragma unroll
    for (int c = 0; c < 8; c++) {
        const int buf = c & 1;
        // prefetch next chunk (global -> regs)
        if (c < 7) {
            const int k0 = (c + 1) * 32;
            #pragma unroll
            for (int it = 0; it < 2; it++) {
                ra[it] = *(const float4*)(Ap + (size_t)(a_row0 + it * 64) * CDIM + k0 + a_ks);
                rb[it] = *(const float4*)(B + (size_t)(k0 + b_k0 + it * 16) * LDB + bn + b_cs);
            }
        }

        // mma over the two k16 steps of this chunk
        #pragma unroll
        for (int kk = 0; kk < 32; kk += 16) {
            wmma::fragment<wmma::matrix_a, 16, 16, 16, bf16, wmma::row_major> ah[2], al[2];
            wmma::fragment<wmma::matrix_b, 16, 16, 16, bf16, wmma::row_major> bh[2], bl[2];
            #pragma unroll
            for (int fi = 0; fi < 2; fi++) {
                const bf16* base = sA + ((size_t)buf * 128 + wm * 32 + fi * 16) * SA_STRIDE + kk;
                wmma::load_matrix_sync(ah[fi], base, SA_STRIDE);
                wmma::load_matrix_sync(al[fi], base + 2 * SA_PLANE, SA_STRIDE);
            }
            #pragma unroll
            for (int fj = 0; fj < 2; fj++) {
                const bf16* base = sB + ((size_t)buf * 32 + kk) * SB_STRIDE + wn * 32 + fj * 16;
                wmma::load_matrix_sync(bh[fj], base, SB_STRIDE);
                wmma::load_matrix_sync(bl[fj], base + 2 * SB_PLANE, SB_STRIDE);
            }
            #pragma unroll
            for (int fi = 0; fi < 2; fi++)
                #pragma unroll
                for (int fj = 0; fj < 2; fj++) {
                    wmma::mma_sync(acc[fi][fj], ah[fi], bh[fj], acc[fi][fj]);
                    wmma::mma_sync(acc[fi][fj], ah[fi], bl[fj], acc[fi][fj]);
                    wmma::mma_sync(acc[fi][fj], al[fi], bh[fj], acc[fi][fj]);
                }
        }

        // split + store next chunk into the other buffer
        if (c < 7) {
            const int nb = (c + 1) & 1;
            #pragma unroll
            for (int it = 0; it < 2; it++) {
                int row = a_row0 + it * 64;
                bf16* ahp = sA + ((size_t)nb * 128 + row) * SA_STRIDE + a_ks;  // hi slot nb
                bf16* alp = ahp + 2 * SA_PLANE;                                // lo slot nb+2
                split_bf16(ra[it].x, ahp[0], alp[0]);
                split_bf16(ra[it].y, ahp[1], alp[1]);
                split_bf16(ra[it].z, ahp[2], alp[2]);
                split_bf16(ra[it].w, ahp[3], alp[3]);
                int k = b_k0 + it * 16;
                bf16* bhp = sB + ((size_t)nb * 32 + k) * SB_STRIDE + b_cs;
                bf16* blp = bhp + 2 * SB_PLANE;
                split_bf16(rb[it].x, bhp[0], blp[0]);
                split_bf16(rb[it].y, bhp[1], blp[1]);
                split_bf16(rb[it].z, bhp[2], blp[2]);
                split_bf16(rb[it].w, bhp[3], blp[3]);
            }
            __syncthreads();
        }
    }

    __syncthreads();   // mainloop smem reads done; safe to overwrite with Cs

    #pragma unroll
    for (int fi = 0; fi < 2; fi++)
        #pragma unroll
        for (int fj = 0; fj < 2; fj++)
            wmma::store_matrix_sync(&Cs[(size_t)(wm * 32 + fi * 16) * 128 + wn * 32 + fj * 16],
                                    acc[fi][fj], 128, wmma::mem_row_major);
    __syncthreads();

    if (MODE == 0) {
        const float scale = 0.17677669529663687f;  // 1/sqrt(32)
        for (int idx = tid; idx < 128 * 128; idx += 512) {
            int i = idx >> 7, jj = idx & 127;
            int j = bn + jj;                         // j = m*256 + h*32 + d
            float v = Cs[(size_t)i * 128 + jj] + bias[j];
            int m = j >> 8, h = (j >> 5) & 7, d = j & 31;
            int r = bm * 128 + i;
            int b = r >> 6, n = r & 63;
            int dst = ((b * NHEAD + h) * NTOK + n) * HD + d;
            if (m == 0)      g_Q[dst] = v * scale;
            else if (m == 1) g_K[dst] = v;
            else             g_V[dst] = v;
        }
    } else {
        for (int idx = tid; idx < 128 * 128; idx += 512) {
            int i = idx >> 7, jj = idx & 127;
            out[(size_t)(bm * 128 + i) * CDIM + bn + jj] =
                Cs[(size_t)i * 128 + jj] + bias[bn + jj];
        }
    }
}

// ---------------------------------------------------------------------------
// Attention kernel (unchanged — verified in R5): one CTA per (window, head).
// ---------------------------------------------------------------------------
struct AttnSmem {
    union {
        struct {
            bf16 Qhi[64][32], Qlo[64][32];
            bf16 Khi[64][32], Klo[64][32];
        } qk;
        struct {
            bf16 Phi[64][64];
            bf16 Plo[64][64];
        } p;
    } u;
    bf16  Vhi[64][32], Vlo[64][32];
    float S[64][64];
};

__global__ __launch_bounds__(128, 4)
void attn_kernel(const float* __restrict__ mask)
{
    __shared__ __align__(32) AttnSmem sm;

    const int tid  = threadIdx.x;
    const int warp = tid >> 5;
    const int lane = tid & 31;

    const int bh = blockIdx.x;
    const int b  = bh >> 3;
    const int h  = bh & 7;

    const float* Qg = g_Q + (size_t)bh * NTOK * HD;
    const float* Kg = g_K + (size_t)bh * NTOK * HD;
    const float* Vg = g_V + (size_t)bh * NTOK * HD;

    for (int i = tid; i < 512; i += 128) {
        int r = i >> 3, c = (i & 7) * 4;
        float4 q = ((const float4*)Qg)[i];
        float4 k = ((const float4*)Kg)[i];
        float4 v = ((const float4*)Vg)[i];
        split_bf16(q.x, sm.u.qk.Qhi[r][c+0], sm.u.qk.Qlo[r][c+0]);
        split_bf16(q.y, sm.u.qk.Qhi[r][c+1], sm.u.qk.Qlo[r][c+1]);
        split_bf16(q.z, sm.u.qk.Qhi[r][c+2], sm.u.qk.Qlo[r][c+2]);
        split_bf16(q.w, sm.u.qk.Qhi[r][c+3], sm.u.qk.Qlo[r][c+3]);
        split_bf16(k.x, sm.u.qk.Khi[r][c+0], sm.u.qk.Klo[r][c+0]);
        split_bf16(k.y, sm.u.qk.Khi[r][c+1], sm.u.qk.Klo[r][c+1]);
        split_bf16(k.z, sm.u.qk.Khi[r][c+2], sm.u.qk.Klo[r][c+2]);
        split_bf16(k.w, sm.u.qk.Khi[r][c+3], sm.u.qk.Klo[r][c+3]);
        split_bf16(v.x, sm.Vhi[r][c+0], sm.Vlo[r][c+0]);
        split_bf16(v.y, sm.Vhi[r][c+1], sm.Vlo[r][c+1]);
        split_bf16(v.z, sm.Vhi[r][c+2], sm.Vlo[r][c+2]);
        split_bf16(v.w, sm.Vhi[r][c+3], sm.Vlo[r][c+3]);
    }
    __syncthreads();

    #pragma unroll
    for (int nt = 0; nt < 4; nt++) {
        wmma::fragment<wmma::accumulator, 16, 16, 16, float> acc;
        wmma::fill_fragment(acc, 0.0f);
        #pragma unroll
        for (int k = 0; k < 32; k += 16) {
            wmma::fragment<wmma::matrix_a, 16, 16, 16, bf16, wmma::row_major> ah, al;
            wmma::fragment<wmma::matrix_b, 16, 16, 16, bf16, wmma::col_major> bh, bl;
            wmma::load_matrix_sync(ah, &sm.u.qk.Qhi[warp * 16][k], 32);
            wmma::load_matrix_sync(al, &sm.u.qk.Qlo[warp * 16][k], 32);
            wmma::load_matrix_sync(bh, &sm.u.qk.Khi[nt * 16][k], 32);
            wmma::load_matrix_sync(bl, &sm.u.qk.Klo[nt * 16][k], 32);
            wmma::mma_sync(acc, ah, bh, acc);
            wmma::mma_sync(acc, ah, bl, acc);
            wmma::mma_sync(acc, al, bh, acc);
        }
        wmma::store_matrix_sync(&sm.S[warp * 16][nt * 16], acc, 64, wmma::mem_row_major);
    }
    __syncthreads();

    {
        const int row = warp * 16 + (lane >> 1);
        const int c0  = (lane & 1) * 32;
        const int w   = b & 63;
        const float* mrow = mask + ((size_t)(w * 64 + row)) * 64 + c0;
        float* srow = &sm.S[row][c0];

        float mx = -1e30f;
        #pragma unroll
        for (int c = 0; c < 32; c++) {
            float v = srow[c] + mrow[c];
            srow[c] = v;
            mx = fmaxf(mx, v);
        }
        mx = fmaxf(mx, __shfl_xor_sync(0xffffffffu, mx, 1));

        float sum = 0.0f;
        float e[32];
        #pragma unroll
        for (int c = 0; c < 32; c++) {
            e[c] = __expf(srow[c] - mx);
            sum += e[c];
        }
        sum += __shfl_xor_sync(0xffffffffu, sum, 1);
        float inv = 1.0f / sum;
        __syncthreads();
        #pragma unroll
        for (int c = 0; c < 32; c++) {
            float p = e[c] * inv;
            split_bf16(p, sm.u.p.Phi[row][c0 + c], sm.u.p.Plo[row][c0 + c]);
        }
    }
    __syncthreads();

    float* Og = g_AO + (size_t)(b * NTOK) * CDIM + h * HD;
    #pragma unroll
    for (int nt = 0; nt < 2; nt++) {
        wmma::fragment<wmma::accumulator, 16, 16, 16, float> acc;
        wmma::fill_fragment(acc, 0.0f);
        #pragma unroll
        for (int k = 0; k < 64; k += 16) {
            wmma::fragment<wmma::matrix_a, 16, 16, 16, bf16, wmma::row_major> ph, pl;
            wmma::fragment<wmma::matrix_b, 16, 16, 16, bf16, wmma::row_major> vh, vl;
            wmma::load_matrix_sync(ph, &sm.u.p.Phi[warp * 16][k], 64);
            wmma::load_matrix_sync(pl, &sm.u.p.Plo[warp * 16][k], 64);
            wmma::load_matrix_sync(vh, &sm.Vhi[k][nt * 16], 32);
            wmma::load_matrix_sync(vl, &sm.Vlo[k][nt * 16], 32);
            wmma::mma_sync(acc, ph, vh, acc);
            wmma::mma_sync(acc, ph, vl, acc);
            wmma::mma_sync(acc, pl, vh, acc);
        }
        wmma::store_matrix_sync(Og + (size_t)(warp * 16) * CDIM + nt * 16, acc, CDIM,
                                wmma::mem_row_major);
    }
}

extern "C" void kernel_launch(void* const* d_in, const int* in_sizes, int n_in,
                              void* d_out, int out_size)
{
    const int elems[6] = {16777216, 262144, 196608, 768, 65536, 256};
    const float* p[6] = {nullptr, nullptr, nullptr, nullptr, nullptr, nullptr};
    bool done = false;
    for (int pass = 0; pass < 2 && !done; pass++) {
        long long mult = (pass == 0) ? 1 : 4;
        const float* q[6] = {nullptr, nullptr, nullptr, nullptr, nullptr, nullptr};
        for (int i = 0; i < n_in; i++)
            for (int j = 0; j < 6; j++)
                if ((long long)in_sizes[i] == (long long)elems[j] * mult && q[j] == nullptr)
                    q[j] = (const float*)d_in[i];
        bool all = true;
        for (int j = 0; j < 6; j++) if (q[j] == nullptr) all = false;
        if (all) { for (int j = 0; j < 6; j++) p[j] = q[j]; done = true; }
    }
    if (!done)
        for (int j = 0; j < 6 && j < n_in; j++) p[j] = (const float*)d_in[j];

    const float* x      = p[0];
    const float* mask   = p[1];
    const float* w_qkv  = p[2];
    const float* b_qkv  = p[3];
    const float* w_proj = p[4];
    const float* b_proj = p[5];
    float* out = (float*)d_out;

    // opt into >48KB dynamic smem (host attribute set; capture-safe, idempotent)
    cudaFuncSetAttribute(gemm_bf16x3_kernel<768, 0>,
                         cudaFuncAttributeMaxDynamicSharedMemorySize, GEMM_SMEM);
    cudaFuncSetAttribute(gemm_bf16x3_kernel<CDIM, 1>,
                         cudaFuncAttributeMaxDynamicSharedMemorySize, GEMM_SMEM);

    // 1) QKV projection: (65536 x 256) @ (256 x 768) -> g_Q/g_K/g_V
    {
        dim3 grid(768 / 128, MROWS / 128);
        gemm_bf16x3_kernel<768, 0><<<grid, 512, GEMM_SMEM>>>(x, w_qkv, b_qkv, nullptr);
    }
    // 2) Windowed attention
    attn_kernel<<<NWIN * NHEAD, 128>>>(mask);
    // 3) Output projection: g_AO @ w_proj + b_proj -> out
    {
        dim3 grid(CDIM / 128, MROWS / 128);
        gemm_bf16x3_kernel<CDIM, 1><<<grid, 512, GEMM_SMEM>>>(nullptr, w_proj, b_proj, out);
    }
}